// round 15
// baseline (speedup 1.0000x reference)
#include <cuda_runtime.h>
#include <cuda_bf16.h>
#include <cstdint>

#define BROWS 8192
#define DDIM  2048
#define KCOLS 512
#define NPTS  17
#define DT    (2.0f / 17.0f)

// ---- GEMM tiling ----
#define BM 128
#define BN 128
#define BK 32
#define KITER (DDIM / BK)          // 64
#define TSTRIDE 40                 // bf16 halves per smem row (32 data + 8 pad)
#define TILEB (128 * TSTRIDE * 2)  // 10240 bytes per tile
#define OAH 0
#define OBH (1 * TILEB)
#define STAGEB (2 * TILEB)         // 20480 bytes per stage
#define NSTAGE 3
#define GEMM_SMEM (NSTAGE * STAGEB)  // 61440

// ---- device scratch ----
__device__ float g_norm2[KCOLS];
__device__ __nv_bfloat16 g_A_hi[(size_t)BROWS * DDIM];
__device__ __nv_bfloat16 g_Bt_hi[KCOLS * DDIM];   // [n][k] normalized bf16
__device__ float g_proj[(size_t)BROWS * KCOLS];
__device__ float g_stat[2 * KCOLS];
__device__ float g_ab[2 * KCOLS];
__device__ float g_ecfR[NPTS * KCOLS];
__device__ float g_ecfI[NPTS * KCOLS];

// ---- helpers ----
__device__ __forceinline__ uint32_t smem_u32(const void* p) {
    uint32_t a;
    asm("{ .reg .u64 t; cvta.to.shared.u64 t, %1; cvt.u32.u64 %0, t; }" : "=r"(a) : "l"(p));
    return a;
}
__device__ __forceinline__ void cp16(uint32_t dst, const void* src) {
    asm volatile("cp.async.cg.shared.global [%0], [%1], 16;" :: "r"(dst), "l"(src));
}
#define CP_COMMIT() asm volatile("cp.async.commit_group;" ::: "memory")
#define CP_WAIT1()  asm volatile("cp.async.wait_group 1;" ::: "memory")

__device__ __forceinline__ void ldsm4(uint32_t* r, uint32_t addr) {
    asm volatile("ldmatrix.sync.aligned.m8n8.x4.shared.b16 {%0,%1,%2,%3}, [%4];"
                 : "=r"(r[0]), "=r"(r[1]), "=r"(r[2]), "=r"(r[3]) : "r"(addr));
}
__device__ __forceinline__ void mma16816(float* d, const uint32_t* a, const uint32_t* b) {
    asm volatile("mma.sync.aligned.m16n8k16.row.col.f32.bf16.bf16.f32 "
                 "{%0,%1,%2,%3}, {%4,%5,%6,%7}, {%8,%9}, {%0,%1,%2,%3};"
                 : "+f"(d[0]), "+f"(d[1]), "+f"(d[2]), "+f"(d[3])
                 : "r"(a[0]), "r"(a[1]), "r"(a[2]), "r"(a[3]), "r"(b[0]), "r"(b[1]));
}

typedef unsigned long long ull;
__device__ __forceinline__ ull ffma2(ull a, ull b, ull c) {
    ull d; asm("fma.rn.f32x2 %0, %1, %2, %3;" : "=l"(d) : "l"(a), "l"(b), "l"(c)); return d;
}
__device__ __forceinline__ ull mul2(ull a, ull b) {
    ull d; asm("mul.rn.f32x2 %0, %1, %2;" : "=l"(d) : "l"(a), "l"(b)); return d;
}
__device__ __forceinline__ ull add2(ull a, ull b) {
    ull d; asm("add.rn.f32x2 %0, %1, %2;" : "=l"(d) : "l"(a), "l"(b)); return d;
}
__device__ __forceinline__ ull dup2(float a) {
    ull r; asm("mov.b64 %0, {%1, %1};" : "=l"(r) : "f"(a)); return r;
}
__device__ __forceinline__ ull pack2(float lo, float hi) {
    ull r; asm("mov.b64 %0, {%1, %2};" : "=l"(r) : "f"(lo), "f"(hi)); return r;
}
__device__ __forceinline__ float2 unpack2(ull v) {
    float2 r; asm("mov.b64 {%0, %1}, %2;" : "=f"(r.x), "=f"(r.y) : "l"(v)); return r;
}
__device__ __forceinline__ ull neg2(ull v) { return v ^ 0x8000000080000000ULL; }

// -------- K0: zero accumulators --------
__global__ void k_zero() {
    int i = blockIdx.x * blockDim.x + threadIdx.x;
    if (i < KCOLS) g_norm2[i] = 0.f;
    if (i < 2 * KCOLS) g_stat[i] = 0.f;
    if (i < NPTS * KCOLS) { g_ecfR[i] = 0.f; g_ecfI[i] = 0.f; }
}

// -------- K1: column squared norms of directions --------
__global__ void k_norm2(const float* __restrict__ dir) {
    int k  = (blockIdx.x & 1) * 256 + threadIdx.x;
    int d0 = (blockIdx.x >> 1) * 32;
    float s = 0.f;
#pragma unroll 8
    for (int d = 0; d < 32; d++) {
        float v = dir[(size_t)(d0 + d) * KCOLS + k];
        s = fmaf(v, v, s);
    }
    atomicAdd(&g_norm2[k], s);
}

// -------- K2: normalize + transpose + bf16 round of directions --------
__global__ void __launch_bounds__(256) k_prepB(const float* __restrict__ dir) {
    __shared__ float s[64][65];
    int t = threadIdx.x;
    int n0t = blockIdx.x * 64;
    int d0  = blockIdx.y * 64;
#pragma unroll
    for (int jj = 0; jj < 4; jj++) {
        int flat = jj * 256 + t;
        int d = flat >> 4;
        int nq = flat & 15;
        float4 v = *(const float4*)(dir + (size_t)(d0 + d) * KCOLS + n0t + nq * 4);
        s[d][nq * 4 + 0] = v.x; s[d][nq * 4 + 1] = v.y;
        s[d][nq * 4 + 2] = v.z; s[d][nq * 4 + 3] = v.w;
    }
    __syncthreads();
#pragma unroll
    for (int jj = 0; jj < 4; jj++) {
        int flat = jj * 256 + t;
        int n = flat >> 4;
        int dq = flat & 15;
        float rn = rsqrtf(fmaxf(g_norm2[n0t + n], 1e-24f));
        float x0 = s[dq * 4 + 0][n] * rn, x1 = s[dq * 4 + 1][n] * rn;
        float x2 = s[dq * 4 + 2][n] * rn, x3 = s[dq * 4 + 3][n] * rn;
        __nv_bfloat162 h01 = __floats2bfloat162_rn(x0, x1);
        __nv_bfloat162 h23 = __floats2bfloat162_rn(x2, x3);
        size_t o = (size_t)(n0t + n) * DDIM + d0 + dq * 4;
        *(uint2*)(g_Bt_hi + o) = make_uint2(*(uint32_t*)&h01, *(uint32_t*)&h23);
    }
}

// -------- K3: round A to bf16 --------
__global__ void __launch_bounds__(256) k_prepA(const float* __restrict__ A) {
    size_t idx = ((size_t)blockIdx.x * 256 + threadIdx.x) * 8;
    float4 v0 = *(const float4*)(A + idx);
    float4 v1 = *(const float4*)(A + idx + 4);
    __nv_bfloat162 h01 = __floats2bfloat162_rn(v0.x, v0.y);
    __nv_bfloat162 h23 = __floats2bfloat162_rn(v0.z, v0.w);
    __nv_bfloat162 h45 = __floats2bfloat162_rn(v1.x, v1.y);
    __nv_bfloat162 h67 = __floats2bfloat162_rn(v1.z, v1.w);
    *(uint4*)(g_A_hi + idx) = make_uint4(*(uint32_t*)&h01, *(uint32_t*)&h23,
                                         *(uint32_t*)&h45, *(uint32_t*)&h67);
}

// -------- K4: HMMA bf16 GEMM (single product) with fused column stats --------
__global__ void __launch_bounds__(256, 2) k_gemm(void) {
    extern __shared__ char smem[];
    const uint32_t sbase = smem_u32(smem);
    const int tid  = threadIdx.x;
    const int lane = tid & 31;
    const int wid  = tid >> 5;
    const int wm   = wid >> 2;       // 0..1  (64-row strip)
    const int wn   = wid & 3;        // 0..3  (32-col strip)
    const int n0 = blockIdx.x * BN;
    const int m0 = blockIdx.y * BM;

    const int lrow = tid >> 1;
    const int lcb  = (tid & 1) * 32;
    const int lke  = (tid & 1) * 16;
    const size_t aoff = (size_t)(m0 + lrow) * DDIM + lke;
    const size_t boff = (size_t)(n0 + lrow) * DDIM + lke;
    const uint32_t ldst = lrow * (TSTRIDE * 2) + lcb;

#define ISSUE(stg, ks) do {                                                   \
    uint32_t _d = sbase + (stg) * STAGEB + ldst;                              \
    size_t _k = (size_t)(ks) * BK;                                            \
    cp16(_d + OAH,      g_A_hi  + aoff + _k);                                 \
    cp16(_d + OAH + 16, g_A_hi  + aoff + _k + 8);                             \
    cp16(_d + OBH,      g_Bt_hi + boff + _k);                                 \
    cp16(_d + OBH + 16, g_Bt_hi + boff + _k + 8);                             \
} while (0)

    float acc[4][4][4];
#pragma unroll
    for (int i = 0; i < 4; i++)
#pragma unroll
        for (int j = 0; j < 4; j++)
#pragma unroll
            for (int q = 0; q < 4; q++) acc[i][j][q] = 0.f;

    const uint32_t aRowB = (wm * 64 + (lane & 15)) * (TSTRIDE * 2) + ((lane >> 4) & 1) * 16;
    const uint32_t bRow4 = (wn * 32 + ((lane >> 4) & 1) * 8 + (lane & 7)) * (TSTRIDE * 2)
                         + ((lane >> 3) & 1) * 16;

    ISSUE(0, 0); CP_COMMIT();
    ISSUE(1, 1); CP_COMMIT();

    for (int i = 0; i < KITER; i++) {
        CP_WAIT1();
        __syncthreads();
        // prefetch into the third slot while computing this one
        if (i + 2 < KITER) {
            int slot = (i + 2) % NSTAGE;
            ISSUE(slot, i + 2);
        }
        CP_COMMIT();
        const uint32_t sb = sbase + (i % NSTAGE) * STAGEB;
#pragma unroll
        for (int k16 = 0; k16 < 2; k16++) {
            const uint32_t kb = k16 * 32;
            uint32_t af[4][4], bh[4][2];
#pragma unroll
            for (int mf = 0; mf < 4; mf++)
                ldsm4(af[mf], sb + OAH + aRowB + mf * 16 * (TSTRIDE * 2) + kb);
#pragma unroll
            for (int p = 0; p < 2; p++) {
                uint32_t tmp[4];
                ldsm4(tmp, sb + OBH + bRow4 + p * 16 * (TSTRIDE * 2) + kb);
                bh[2 * p][0] = tmp[0]; bh[2 * p][1] = tmp[1];
                bh[2 * p + 1][0] = tmp[2]; bh[2 * p + 1][1] = tmp[3];
            }
#pragma unroll
            for (int mf = 0; mf < 4; mf++)
#pragma unroll
                for (int nf = 0; nf < 4; nf++)
                    mma16816(acc[mf][nf], af[mf], bh[nf]);
        }
    }

    // ---- epilogue: store proj + fused column stats ----
    float sc[8], sq[8];
#pragma unroll
    for (int e = 0; e < 8; e++) { sc[e] = 0.f; sq[e] = 0.f; }

#pragma unroll
    for (int mf = 0; mf < 4; mf++) {
        const int m = m0 + wm * 64 + mf * 16 + (lane >> 2);
#pragma unroll
        for (int nf = 0; nf < 4; nf++) {
            const int n = n0 + wn * 32 + nf * 8 + (lane & 3) * 2;
            float* c = acc[mf][nf];
            *(float2*)&g_proj[(size_t)m * KCOLS + n]       = make_float2(c[0], c[1]);
            *(float2*)&g_proj[(size_t)(m + 8) * KCOLS + n] = make_float2(c[2], c[3]);
            sc[nf * 2 + 0] += c[0] + c[2];
            sc[nf * 2 + 1] += c[1] + c[3];
            sq[nf * 2 + 0] += c[0] * c[0] + c[2] * c[2];
            sq[nf * 2 + 1] += c[1] * c[1] + c[3] * c[3];
        }
    }
#pragma unroll
    for (int off = 16; off >= 4; off >>= 1)
#pragma unroll
        for (int e = 0; e < 8; e++) {
            sc[e] += __shfl_down_sync(0xFFFFFFFF, sc[e], off);
            sq[e] += __shfl_down_sync(0xFFFFFFFF, sq[e], off);
        }
    if (lane < 4) {
#pragma unroll
        for (int nf = 0; nf < 4; nf++)
#pragma unroll
            for (int p = 0; p < 2; p++) {
                int col = n0 + wn * 32 + nf * 8 + 2 * lane + p;
                atomicAdd(&g_stat[col],         sc[nf * 2 + p]);
                atomicAdd(&g_stat[KCOLS + col], sq[nf * 2 + p]);
            }
    }
}

// -------- K5: a,b affine --------
__global__ void k_ab() {
    int k = blockIdx.x * blockDim.x + threadIdx.x;
    if (k >= KCOLS) return;
    float sum = g_stat[k];
    float sq  = g_stat[KCOLS + k];
    float mu  = sum * (1.0f / (float)BROWS);
    float var = (sq - (float)BROWS * mu * mu) * (1.0f / (float)(BROWS - 1));
    float sd  = sqrtf(fmaxf(var, 0.f));
    float a   = 1.0f / (sd + 1e-8f);
    g_ab[k]         = DT * a;
    g_ab[KCOLS + k] = DT * (-mu * a);
}

// -------- K6: ECF, Chebyshev recurrence with 2 packed chain sets (4 rows/iter) --------
__global__ void __launch_bounds__(256) k_ecf() {
    __shared__ float part[8][2 * NPTS][32];
    const int lane = threadIdx.x & 31;
    const int w    = threadIdx.x >> 5;
    const int k    = blockIdx.x * 32 + lane;
    const int b0   = blockIdx.y * 512 + w * 64;

    const float a = g_ab[k];
    const float b = g_ab[KCOLS + k];

    const ull ONE = dup2(1.0f);
    const ull NONE = dup2(-1.0f);
    const ull S1 = dup2(-1.6666667e-1f), S2 = dup2(8.3333333e-3f), S3 = dup2(-1.9841270e-4f);
    const ull C1 = dup2(-0.5f), C2 = dup2(4.1666668e-2f), C3 = dup2(-1.3888889e-3f), C4 = dup2(2.4801587e-5f);

    ull accR[NPTS], accI[NPTS];
#pragma unroll
    for (int j = 0; j < NPTS; j++) { accR[j] = 0ULL; accI[j] = 0ULL; }

    for (int r = 0; r < 16; r++) {
        float p0 = g_proj[(size_t)(b0 + r)      * KCOLS + k];
        float p1 = g_proj[(size_t)(b0 + r + 16) * KCOLS + k];
        float p2 = g_proj[(size_t)(b0 + r + 32) * KCOLS + k];
        float p3 = g_proj[(size_t)(b0 + r + 48) * KCOLS + k];
        ull xA  = pack2(fmaf(a, p0, b), fmaf(a, p1, b));
        ull xB  = pack2(fmaf(a, p2, b), fmaf(a, p3, b));
        ull x2A = mul2(xA, xA);
        ull x2B = mul2(xB, xB);
        ull psA = ffma2(x2A, S3, S2); psA = ffma2(x2A, psA, S1); psA = ffma2(x2A, psA, ONE);
        ull psB = ffma2(x2B, S3, S2); psB = ffma2(x2B, psB, S1); psB = ffma2(x2B, psB, ONE);
        ull s1A = mul2(xA, psA);
        ull s1B = mul2(xB, psB);
        ull pcA = ffma2(x2A, C4, C3); pcA = ffma2(x2A, pcA, C2); pcA = ffma2(x2A, pcA, C1);
        ull pcB = ffma2(x2B, C4, C3); pcB = ffma2(x2B, pcB, C2); pcB = ffma2(x2B, pcB, C1);
        ull c1A = ffma2(x2A, pcA, ONE);
        ull c1B = ffma2(x2B, pcB, ONE);

        ull twocA = add2(c1A, c1A), twocB = add2(c1B, c1B);
        ull cA = c1A, sA = s1A, cB = c1B, sB = s1B;
        ull ncpA = NONE, nspA = 0ULL, ncpB = NONE, nspB = 0ULL;
        accR[0] = add2(accR[0], add2(c1A, c1B));
        accI[0] = add2(accI[0], add2(s1A, s1B));
#pragma unroll
        for (int m = 2; m <= NPTS; m++) {
            ull cnA = ffma2(twocA, cA, ncpA);
            ull snA = ffma2(twocA, sA, nspA);
            ull cnB = ffma2(twocB, cB, ncpB);
            ull snB = ffma2(twocB, sB, nspB);
            accR[m - 1] = add2(accR[m - 1], add2(cnA, cnB));
            accI[m - 1] = add2(accI[m - 1], add2(snA, snB));
            ncpA = neg2(cA); nspA = neg2(sA);
            ncpB = neg2(cB); nspB = neg2(sB);
            cA = cnA; sA = snA; cB = cnB; sB = snB;
        }
    }
#pragma unroll
    for (int j = 0; j < NPTS; j++) {
        float2 fr = unpack2(accR[j]);
        float2 fi = unpack2(accI[j]);
        part[w][j][lane]        = fr.x + fr.y;
        part[w][NPTS + j][lane] = fi.x + fi.y;
    }
    __syncthreads();
    for (int e = threadIdx.x; e < 2 * NPTS * 32; e += 256) {
        int jj = e >> 5;
        int ln = e & 31;
        float s = 0.f;
#pragma unroll
        for (int ww = 0; ww < 8; ww++) s += part[ww][jj][ln];
        int kk = blockIdx.x * 32 + ln;
        if (jj < NPTS) atomicAdd(&g_ecfR[jj * KCOLS + kk], s);
        else           atomicAdd(&g_ecfI[(jj - NPTS) * KCOLS + kk], s);
    }
}

// -------- K7: final scalar --------
__global__ void k_final(float* __restrict__ out) {
    __shared__ float sd[KCOLS];
    int k = threadIdx.x;
    float acc = 0.f;
#pragma unroll
    for (int j = 0; j < NPTS; j++) {
        float t   = (float)(j + 1) * DT;
        float er  = g_ecfR[j * KCOLS + k] * (1.0f / (float)BROWS);
        float ei  = g_ecfI[j * KCOLS + k] * (1.0f / (float)BROWS);
        float tcf = expf(-0.5f * t * t);
        float wq  = (j == 0 || j == NPTS - 1) ? (DT * 0.5f) : DT;
        float d   = er - tcf;
        acc = fmaf(wq, fmaf(d, d, ei * ei), acc);
    }
    sd[k] = acc;
    __syncthreads();
    for (int s = 256; s > 0; s >>= 1) {
        if (k < s) sd[k] += sd[k + s];
        __syncthreads();
    }
    if (k == 0) out[0] = sd[0] * (1.0f / (float)KCOLS);
}

extern "C" void kernel_launch(void* const* d_in, const int* in_sizes, int n_in,
                              void* d_out, int out_size) {
    const float* emb = (const float*)d_in[0];   // (8192, 2048)
    const float* dir = (const float*)d_in[1];   // (2048, 512)
    float* out = (float*)d_out;

    cudaFuncSetAttribute(k_gemm, cudaFuncAttributeMaxDynamicSharedMemorySize, GEMM_SMEM);

    k_zero<<<(NPTS * KCOLS + 255) / 256, 256>>>();
    k_norm2<<<128, 256>>>(dir);
    k_prepB<<<dim3(KCOLS / 64, DDIM / 64), 256>>>(dir);
    k_prepA<<<(BROWS * DDIM) / (256 * 8), 256>>>(emb);
    k_gemm<<<dim3(KCOLS / BN, BROWS / BM), 256, GEMM_SMEM>>>();
    k_ab<<<2, 256>>>();
    k_ecf<<<dim3(KCOLS / 32, BROWS / 512), 256>>>();
    k_final<<<1, KCOLS>>>(out);
}

// round 16
// speedup vs baseline: 1.0060x; 1.0060x over previous
#include <cuda_runtime.h>
#include <cuda_bf16.h>
#include <cstdint>

#define BROWS 8192
#define DDIM  2048
#define KCOLS 512
#define NPTS  17
#define DT    (2.0f / 17.0f)

// ---- GEMM tiling ----
#define BM 128
#define BN 128
#define BK 32
#define KITER (DDIM / BK)          // 64
#define TSTRIDE 40                 // bf16 halves per smem row (32 data + 8 pad)
#define TILEB (128 * TSTRIDE * 2)  // 10240 bytes per tile
#define OAH 0
#define OBH (1 * TILEB)
#define STAGEB (2 * TILEB)         // 20480 bytes per stage
#define NSTAGE 3
#define GEMM_SMEM (NSTAGE * STAGEB)  // 61440

// ---- device scratch ----
__device__ float g_norm2[KCOLS];
__device__ __nv_bfloat16 g_A_hi[(size_t)BROWS * DDIM];
__device__ __nv_bfloat16 g_Bt_hi[KCOLS * DDIM];   // [n][k] normalized bf16
__device__ float g_proj[(size_t)BROWS * KCOLS];
__device__ float g_stat[2 * KCOLS];
__device__ float g_ab[2 * KCOLS];
__device__ float g_ecfR[NPTS * KCOLS];
__device__ float g_ecfI[NPTS * KCOLS];

// ---- helpers ----
__device__ __forceinline__ uint32_t smem_u32(const void* p) {
    uint32_t a;
    asm("{ .reg .u64 t; cvta.to.shared.u64 t, %1; cvt.u32.u64 %0, t; }" : "=r"(a) : "l"(p));
    return a;
}
__device__ __forceinline__ void cp16(uint32_t dst, const void* src) {
    asm volatile("cp.async.cg.shared.global [%0], [%1], 16;" :: "r"(dst), "l"(src));
}
#define CP_COMMIT() asm volatile("cp.async.commit_group;" ::: "memory")
#define CP_WAIT1()  asm volatile("cp.async.wait_group 1;" ::: "memory")

__device__ __forceinline__ void ldsm4(uint32_t* r, uint32_t addr) {
    asm volatile("ldmatrix.sync.aligned.m8n8.x4.shared.b16 {%0,%1,%2,%3}, [%4];"
                 : "=r"(r[0]), "=r"(r[1]), "=r"(r[2]), "=r"(r[3]) : "r"(addr));
}
__device__ __forceinline__ void mma16816(float* d, const uint32_t* a, const uint32_t* b) {
    asm volatile("mma.sync.aligned.m16n8k16.row.col.f32.bf16.bf16.f32 "
                 "{%0,%1,%2,%3}, {%4,%5,%6,%7}, {%8,%9}, {%0,%1,%2,%3};"
                 : "+f"(d[0]), "+f"(d[1]), "+f"(d[2]), "+f"(d[3])
                 : "r"(a[0]), "r"(a[1]), "r"(a[2]), "r"(a[3]), "r"(b[0]), "r"(b[1]));
}

typedef unsigned long long ull;
__device__ __forceinline__ ull ffma2(ull a, ull b, ull c) {
    ull d; asm("fma.rn.f32x2 %0, %1, %2, %3;" : "=l"(d) : "l"(a), "l"(b), "l"(c)); return d;
}
__device__ __forceinline__ ull mul2(ull a, ull b) {
    ull d; asm("mul.rn.f32x2 %0, %1, %2;" : "=l"(d) : "l"(a), "l"(b)); return d;
}
__device__ __forceinline__ ull add2(ull a, ull b) {
    ull d; asm("add.rn.f32x2 %0, %1, %2;" : "=l"(d) : "l"(a), "l"(b)); return d;
}
__device__ __forceinline__ ull dup2(float a) {
    ull r; asm("mov.b64 %0, {%1, %1};" : "=l"(r) : "f"(a)); return r;
}
__device__ __forceinline__ ull pack2(float lo, float hi) {
    ull r; asm("mov.b64 %0, {%1, %2};" : "=l"(r) : "f"(lo), "f"(hi)); return r;
}
__device__ __forceinline__ float2 unpack2(ull v) {
    float2 r; asm("mov.b64 {%0, %1}, %2;" : "=f"(r.x), "=f"(r.y) : "l"(v)); return r;
}
__device__ __forceinline__ ull neg2(ull v) { return v ^ 0x8000000080000000ULL; }

// -------- K0: zero accumulators --------
__global__ void k_zero() {
    int i = blockIdx.x * blockDim.x + threadIdx.x;
    if (i < KCOLS) g_norm2[i] = 0.f;
    if (i < 2 * KCOLS) g_stat[i] = 0.f;
    if (i < NPTS * KCOLS) { g_ecfR[i] = 0.f; g_ecfI[i] = 0.f; }
}

// -------- K1: column squared norms of directions --------
__global__ void k_norm2(const float* __restrict__ dir) {
    int k  = (blockIdx.x & 1) * 256 + threadIdx.x;
    int d0 = (blockIdx.x >> 1) * 32;
    float s = 0.f;
#pragma unroll 8
    for (int d = 0; d < 32; d++) {
        float v = dir[(size_t)(d0 + d) * KCOLS + k];
        s = fmaf(v, v, s);
    }
    atomicAdd(&g_norm2[k], s);
}

// -------- K2: normalize + transpose + bf16 round of directions --------
__global__ void __launch_bounds__(256) k_prepB(const float* __restrict__ dir) {
    __shared__ float s[64][65];
    int t = threadIdx.x;
    int n0t = blockIdx.x * 64;
    int d0  = blockIdx.y * 64;
#pragma unroll
    for (int jj = 0; jj < 4; jj++) {
        int flat = jj * 256 + t;
        int d = flat >> 4;
        int nq = flat & 15;
        float4 v = *(const float4*)(dir + (size_t)(d0 + d) * KCOLS + n0t + nq * 4);
        s[d][nq * 4 + 0] = v.x; s[d][nq * 4 + 1] = v.y;
        s[d][nq * 4 + 2] = v.z; s[d][nq * 4 + 3] = v.w;
    }
    __syncthreads();
#pragma unroll
    for (int jj = 0; jj < 4; jj++) {
        int flat = jj * 256 + t;
        int n = flat >> 4;
        int dq = flat & 15;
        float rn = rsqrtf(fmaxf(g_norm2[n0t + n], 1e-24f));
        float x0 = s[dq * 4 + 0][n] * rn, x1 = s[dq * 4 + 1][n] * rn;
        float x2 = s[dq * 4 + 2][n] * rn, x3 = s[dq * 4 + 3][n] * rn;
        __nv_bfloat162 h01 = __floats2bfloat162_rn(x0, x1);
        __nv_bfloat162 h23 = __floats2bfloat162_rn(x2, x3);
        size_t o = (size_t)(n0t + n) * DDIM + d0 + dq * 4;
        *(uint2*)(g_Bt_hi + o) = make_uint2(*(uint32_t*)&h01, *(uint32_t*)&h23);
    }
}

// -------- K3: round A to bf16 --------
__global__ void __launch_bounds__(256) k_prepA(const float* __restrict__ A) {
    size_t idx = ((size_t)blockIdx.x * 256 + threadIdx.x) * 8;
    float4 v0 = *(const float4*)(A + idx);
    float4 v1 = *(const float4*)(A + idx + 4);
    __nv_bfloat162 h01 = __floats2bfloat162_rn(v0.x, v0.y);
    __nv_bfloat162 h23 = __floats2bfloat162_rn(v0.z, v0.w);
    __nv_bfloat162 h45 = __floats2bfloat162_rn(v1.x, v1.y);
    __nv_bfloat162 h67 = __floats2bfloat162_rn(v1.z, v1.w);
    *(uint4*)(g_A_hi + idx) = make_uint4(*(uint32_t*)&h01, *(uint32_t*)&h23,
                                         *(uint32_t*)&h45, *(uint32_t*)&h67);
}

// -------- K4: HMMA bf16 GEMM (single product) with fused column stats --------
__global__ void __launch_bounds__(256, 2) k_gemm(void) {
    extern __shared__ char smem[];
    const uint32_t sbase = smem_u32(smem);
    const int tid  = threadIdx.x;
    const int lane = tid & 31;
    const int wid  = tid >> 5;
    const int wm   = wid >> 2;       // 0..1  (64-row strip)
    const int wn   = wid & 3;        // 0..3  (32-col strip)
    const int n0 = blockIdx.x * BN;
    const int m0 = blockIdx.y * BM;

    const int lrow = tid >> 1;
    const int lcb  = (tid & 1) * 32;
    const int lke  = (tid & 1) * 16;
    const size_t aoff = (size_t)(m0 + lrow) * DDIM + lke;
    const size_t boff = (size_t)(n0 + lrow) * DDIM + lke;
    const uint32_t ldst = lrow * (TSTRIDE * 2) + lcb;

#define ISSUE(stg, ks) do {                                                   \
    uint32_t _d = sbase + (stg) * STAGEB + ldst;                              \
    size_t _k = (size_t)(ks) * BK;                                            \
    cp16(_d + OAH,      g_A_hi  + aoff + _k);                                 \
    cp16(_d + OAH + 16, g_A_hi  + aoff + _k + 8);                             \
    cp16(_d + OBH,      g_Bt_hi + boff + _k);                                 \
    cp16(_d + OBH + 16, g_Bt_hi + boff + _k + 8);                             \
} while (0)

    float acc[4][4][4];
#pragma unroll
    for (int i = 0; i < 4; i++)
#pragma unroll
        for (int j = 0; j < 4; j++)
#pragma unroll
            for (int q = 0; q < 4; q++) acc[i][j][q] = 0.f;

    const uint32_t aRowB = (wm * 64 + (lane & 15)) * (TSTRIDE * 2) + ((lane >> 4) & 1) * 16;
    const uint32_t bRow4 = (wn * 32 + ((lane >> 4) & 1) * 8 + (lane & 7)) * (TSTRIDE * 2)
                         + ((lane >> 3) & 1) * 16;

    ISSUE(0, 0); CP_COMMIT();
    ISSUE(1, 1); CP_COMMIT();

    for (int i = 0; i < KITER; i++) {
        CP_WAIT1();
        __syncthreads();
        // prefetch into the third slot while computing this one
        if (i + 2 < KITER) {
            int slot = (i + 2) % NSTAGE;
            ISSUE(slot, i + 2);
        }
        CP_COMMIT();
        const uint32_t sb = sbase + (i % NSTAGE) * STAGEB;
#pragma unroll
        for (int k16 = 0; k16 < 2; k16++) {
            const uint32_t kb = k16 * 32;
            uint32_t af[4][4], bh[4][2];
#pragma unroll
            for (int mf = 0; mf < 4; mf++)
                ldsm4(af[mf], sb + OAH + aRowB + mf * 16 * (TSTRIDE * 2) + kb);
#pragma unroll
            for (int p = 0; p < 2; p++) {
                uint32_t tmp[4];
                ldsm4(tmp, sb + OBH + bRow4 + p * 16 * (TSTRIDE * 2) + kb);
                bh[2 * p][0] = tmp[0]; bh[2 * p][1] = tmp[1];
                bh[2 * p + 1][0] = tmp[2]; bh[2 * p + 1][1] = tmp[3];
            }
#pragma unroll
            for (int mf = 0; mf < 4; mf++)
#pragma unroll
                for (int nf = 0; nf < 4; nf++)
                    mma16816(acc[mf][nf], af[mf], bh[nf]);
        }
    }

    // ---- epilogue: store proj + fused column stats ----
    float sc[8], sq[8];
#pragma unroll
    for (int e = 0; e < 8; e++) { sc[e] = 0.f; sq[e] = 0.f; }

#pragma unroll
    for (int mf = 0; mf < 4; mf++) {
        const int m = m0 + wm * 64 + mf * 16 + (lane >> 2);
#pragma unroll
        for (int nf = 0; nf < 4; nf++) {
            const int n = n0 + wn * 32 + nf * 8 + (lane & 3) * 2;
            float* c = acc[mf][nf];
            *(float2*)&g_proj[(size_t)m * KCOLS + n]       = make_float2(c[0], c[1]);
            *(float2*)&g_proj[(size_t)(m + 8) * KCOLS + n] = make_float2(c[2], c[3]);
            sc[nf * 2 + 0] += c[0] + c[2];
            sc[nf * 2 + 1] += c[1] + c[3];
            sq[nf * 2 + 0] += c[0] * c[0] + c[2] * c[2];
            sq[nf * 2 + 1] += c[1] * c[1] + c[3] * c[3];
        }
    }
#pragma unroll
    for (int off = 16; off >= 4; off >>= 1)
#pragma unroll
        for (int e = 0; e < 8; e++) {
            sc[e] += __shfl_down_sync(0xFFFFFFFF, sc[e], off);
            sq[e] += __shfl_down_sync(0xFFFFFFFF, sq[e], off);
        }
    if (lane < 4) {
#pragma unroll
        for (int nf = 0; nf < 4; nf++)
#pragma unroll
            for (int p = 0; p < 2; p++) {
                int col = n0 + wn * 32 + nf * 8 + 2 * lane + p;
                atomicAdd(&g_stat[col],         sc[nf * 2 + p]);
                atomicAdd(&g_stat[KCOLS + col], sq[nf * 2 + p]);
            }
    }
}

// -------- K5: a,b affine --------
__global__ void k_ab() {
    int k = blockIdx.x * blockDim.x + threadIdx.x;
    if (k >= KCOLS) return;
    float sum = g_stat[k];
    float sq  = g_stat[KCOLS + k];
    float mu  = sum * (1.0f / (float)BROWS);
    float var = (sq - (float)BROWS * mu * mu) * (1.0f / (float)(BROWS - 1));
    float sd  = sqrtf(fmaxf(var, 0.f));
    float a   = 1.0f / (sd + 1e-8f);
    g_ab[k]         = DT * a;
    g_ab[KCOLS + k] = DT * (-mu * a);
}

// -------- K6: ECF, Chebyshev recurrence with 2 packed chain sets (4 rows/iter) --------
__global__ void __launch_bounds__(256) k_ecf() {
    __shared__ float part[8][2 * NPTS][32];
    const int lane = threadIdx.x & 31;
    const int w    = threadIdx.x >> 5;
    const int k    = blockIdx.x * 32 + lane;
    const int b0   = blockIdx.y * 512 + w * 64;

    const float a = g_ab[k];
    const float b = g_ab[KCOLS + k];

    const ull ONE = dup2(1.0f);
    const ull NONE = dup2(-1.0f);
    const ull S1 = dup2(-1.6666667e-1f), S2 = dup2(8.3333333e-3f), S3 = dup2(-1.9841270e-4f);
    const ull C1 = dup2(-0.5f), C2 = dup2(4.1666668e-2f), C3 = dup2(-1.3888889e-3f), C4 = dup2(2.4801587e-5f);

    ull accR[NPTS], accI[NPTS];
#pragma unroll
    for (int j = 0; j < NPTS; j++) { accR[j] = 0ULL; accI[j] = 0ULL; }

    for (int r = 0; r < 16; r++) {
        float p0 = g_proj[(size_t)(b0 + r)      * KCOLS + k];
        float p1 = g_proj[(size_t)(b0 + r + 16) * KCOLS + k];
        float p2 = g_proj[(size_t)(b0 + r + 32) * KCOLS + k];
        float p3 = g_proj[(size_t)(b0 + r + 48) * KCOLS + k];
        ull xA  = pack2(fmaf(a, p0, b), fmaf(a, p1, b));
        ull xB  = pack2(fmaf(a, p2, b), fmaf(a, p3, b));
        ull x2A = mul2(xA, xA);
        ull x2B = mul2(xB, xB);
        ull psA = ffma2(x2A, S3, S2); psA = ffma2(x2A, psA, S1); psA = ffma2(x2A, psA, ONE);
        ull psB = ffma2(x2B, S3, S2); psB = ffma2(x2B, psB, S1); psB = ffma2(x2B, psB, ONE);
        ull s1A = mul2(xA, psA);
        ull s1B = mul2(xB, psB);
        ull pcA = ffma2(x2A, C4, C3); pcA = ffma2(x2A, pcA, C2); pcA = ffma2(x2A, pcA, C1);
        ull pcB = ffma2(x2B, C4, C3); pcB = ffma2(x2B, pcB, C2); pcB = ffma2(x2B, pcB, C1);
        ull c1A = ffma2(x2A, pcA, ONE);
        ull c1B = ffma2(x2B, pcB, ONE);

        ull twocA = add2(c1A, c1A), twocB = add2(c1B, c1B);
        ull cA = c1A, sA = s1A, cB = c1B, sB = s1B;
        ull ncpA = NONE, nspA = 0ULL, ncpB = NONE, nspB = 0ULL;
        accR[0] = add2(accR[0], add2(c1A, c1B));
        accI[0] = add2(accI[0], add2(s1A, s1B));
#pragma unroll
        for (int m = 2; m <= NPTS; m++) {
            ull cnA = ffma2(twocA, cA, ncpA);
            ull snA = ffma2(twocA, sA, nspA);
            ull cnB = ffma2(twocB, cB, ncpB);
            ull snB = ffma2(twocB, sB, nspB);
            accR[m - 1] = add2(accR[m - 1], add2(cnA, cnB));
            accI[m - 1] = add2(accI[m - 1], add2(snA, snB));
            ncpA = neg2(cA); nspA = neg2(sA);
            ncpB = neg2(cB); nspB = neg2(sB);
            cA = cnA; sA = snA; cB = cnB; sB = snB;
        }
    }
#pragma unroll
    for (int j = 0; j < NPTS; j++) {
        float2 fr = unpack2(accR[j]);
        float2 fi = unpack2(accI[j]);
        part[w][j][lane]        = fr.x + fr.y;
        part[w][NPTS + j][lane] = fi.x + fi.y;
    }
    __syncthreads();
    for (int e = threadIdx.x; e < 2 * NPTS * 32; e += 256) {
        int jj = e >> 5;
        int ln = e & 31;
        float s = 0.f;
#pragma unroll
        for (int ww = 0; ww < 8; ww++) s += part[ww][jj][ln];
        int kk = blockIdx.x * 32 + ln;
        if (jj < NPTS) atomicAdd(&g_ecfR[jj * KCOLS + kk], s);
        else           atomicAdd(&g_ecfI[(jj - NPTS) * KCOLS + kk], s);
    }
}

// -------- K7: final scalar --------
__global__ void k_final(float* __restrict__ out) {
    __shared__ float sd[KCOLS];
    int k = threadIdx.x;
    float acc = 0.f;
#pragma unroll
    for (int j = 0; j < NPTS; j++) {
        float t   = (float)(j + 1) * DT;
        float er  = g_ecfR[j * KCOLS + k] * (1.0f / (float)BROWS);
        float ei  = g_ecfI[j * KCOLS + k] * (1.0f / (float)BROWS);
        float tcf = expf(-0.5f * t * t);
        float wq  = (j == 0 || j == NPTS - 1) ? (DT * 0.5f) : DT;
        float d   = er - tcf;
        acc = fmaf(wq, fmaf(d, d, ei * ei), acc);
    }
    sd[k] = acc;
    __syncthreads();
    for (int s = 256; s > 0; s >>= 1) {
        if (k < s) sd[k] += sd[k + s];
        __syncthreads();
    }
    if (k == 0) out[0] = sd[0] * (1.0f / (float)KCOLS);
}

extern "C" void kernel_launch(void* const* d_in, const int* in_sizes, int n_in,
                              void* d_out, int out_size) {
    const float* emb = (const float*)d_in[0];   // (8192, 2048)
    const float* dir = (const float*)d_in[1];   // (2048, 512)
    float* out = (float*)d_out;

    cudaFuncSetAttribute(k_gemm, cudaFuncAttributeMaxDynamicSharedMemorySize, GEMM_SMEM);

    k_zero<<<(NPTS * KCOLS + 255) / 256, 256>>>();
    k_norm2<<<128, 256>>>(dir);
    k_prepB<<<dim3(KCOLS / 64, DDIM / 64), 256>>>(dir);
    k_prepA<<<(BROWS * DDIM) / (256 * 8), 256>>>(emb);
    k_gemm<<<dim3(KCOLS / BN, BROWS / BM), 256, GEMM_SMEM>>>();
    k_ab<<<2, 256>>>();
    k_ecf<<<dim3(KCOLS / 32, BROWS / 512), 256>>>();
    k_final<<<1, KCOLS>>>(out);
}